// round 6
// baseline (speedup 1.0000x reference)
#include <cuda_runtime.h>
#include <cstdint>

#define NPG  1024
#define TILE 128
#define HD   64

__device__ __forceinline__ int prev_node(int j) {
    return ((j & (NPG - 1)) == 0) ? j + NPG - 1 : j - 1;
}

__device__ __forceinline__ uint32_t f2tf32(float f) {
    uint32_t r;
    asm("cvt.rna.tf32.f32 %0, %1;" : "=r"(r) : "f"(f));
    return r;
}

__device__ __forceinline__ void mma_tf32(float* d, const uint32_t* a, uint32_t b0, uint32_t b1) {
    asm volatile(
        "mma.sync.aligned.m16n8k8.row.col.f32.tf32.tf32.f32 "
        "{%0,%1,%2,%3}, {%4,%5,%6,%7}, {%8,%9}, {%0,%1,%2,%3};"
        : "+f"(d[0]), "+f"(d[1]), "+f"(d[2]), "+f"(d[3])
        : "r"(a[0]), "r"(a[1]), "r"(a[2]), "r"(a[3]), "r"(b0), "r"(b1));
}

__device__ __forceinline__ float dot3(float4 u, float4 w) {
    return fmaf(u.x, w.x, fmaf(u.y, w.y, fmaf(u.z, w.z, w.w)));
}

__global__ void __launch_bounds__(TILE, 3) gnn_mma(
    const float* __restrict__ x,
    const float* __restrict__ W1, const float* __restrict__ b1,
    const float* __restrict__ W2, const float* __restrict__ b2,
    const float* __restrict__ Wl, const float* __restrict__ bl,
    float* __restrict__ out, int NT)
{
    __shared__ float4   su[TILE + 4];   // su[i] = avg input of node (base + i - 1)
    __shared__ float4   w1pk[HD];       // {W1[0][k], W1[1][k], W1[2][k], b1[k]}
    __shared__ float4   hdt[HD];        // {b2[c], Wl[c][0], Wl[c][1], Wl[c][2]}
    __shared__ uint32_t sBf[8 * 4 * 32 * 4];  // W2 tf32 fragments, per-lane chunked

    const int t  = threadIdx.x;
    const int l  = t & 31;
    const int w  = t >> 5;
    const int lq = l >> 2;
    const int lr = l & 3;
    const int c  = (w << 5) + lq;      // base row of this thread's fragments

    if (t < HD) {
        float4 v; v.x = W1[t]; v.y = W1[HD + t]; v.z = W1[2 * HD + t]; v.w = b1[t];
        w1pk[t] = v;
    } else {
        int cc = t - HD;
        float4 h; h.x = b2[cc]; h.y = Wl[3 * cc + 0]; h.z = Wl[3 * cc + 1]; h.w = Wl[3 * cc + 2];
        hdt[cc] = h;
    }

    // ---- W2 -> shared tf32 fragments, chunk layout:
    // idx = kb*512 + q*128 + lane*4 + e ; q = j*2 + (nb>>2), nb = (q&1)*4 + e
    // value = tf32( W2[ kb*8 + (lane&3) + 4*j ][ nb*8 + (lane>>2) ] )
    for (int idx = t; idx < 4096; idx += TILE) {
        int kb  = idx >> 9;
        int rem = idx & 511;
        int q   = rem >> 7;
        int ll  = (rem >> 2) & 31;
        int e   = rem & 3;
        int j   = q >> 1;
        int nb  = (q & 1) * 4 + e;
        int k   = kb * 8 + (ll & 3) + 4 * j;
        int n   = nb * 8 + (ll >> 2);
        sBf[idx] = f2tf32(W2[k * HD + n]);
    }

    const float bl0 = bl[0], bl1 = bl[1], bl2 = bl[2];
    const uint4* sB4 = reinterpret_cast<const uint4*>(sBf);

    for (int tile = blockIdx.x; tile < NT; tile += gridDim.x) {
        const int base = tile * TILE;

        __syncthreads();   // prior tile readers done (also covers sBf init on first iter)
        {
            int node = base + t;
            int p = prev_node(node);
            float4 v;
            v.x = 0.5f * (x[3*node+0] + x[3*p+0]);
            v.y = 0.5f * (x[3*node+1] + x[3*p+1]);
            v.z = 0.5f * (x[3*node+2] + x[3*p+2]);
            v.w = 0.0f;
            su[t + 1] = v;
            if (t == 0) {
                int n0 = p, p0 = prev_node(p);
                float4 h;
                h.x = 0.5f * (x[3*n0+0] + x[3*p0+0]);
                h.y = 0.5f * (x[3*n0+1] + x[3*p0+1]);
                h.z = 0.5f * (x[3*n0+2] + x[3*p0+2]);
                h.w = 0.0f;
                su[0] = h;
            }
        }
        __syncthreads();

        // hoist the 8 u-vectors this thread needs (rows c+{0,8,16,24}, cur & prev)
        float4 up[4], uc[4];
        #pragma unroll
        for (int i = 0; i < 4; i++) {
            int r = c + 8 * i;
            up[i] = su[r];
            uc[i] = su[r + 1];
        }

        float dacc[2][8][4];
        #pragma unroll
        for (int mb = 0; mb < 2; mb++)
            #pragma unroll
            for (int nb = 0; nb < 8; nb++)
                #pragma unroll
                for (int j = 0; j < 4; j++) dacc[mb][nb][j] = 0.0f;

        // ---- k-loop: A fragments on the fly, B fragments streamed from shared
        #pragma unroll
        for (int kb = 0; kb < 8; kb++) {
            // B chunks: q0 = j0 nb0-3, q1 = j0 nb4-7, q2 = j1 nb0-3, q3 = j1 nb4-7
            uint4 c0 = sB4[(kb * 4 + 0) * 32 + l];
            uint4 c1 = sB4[(kb * 4 + 1) * 32 + l];
            uint4 c2 = sB4[(kb * 4 + 2) * 32 + l];
            uint4 c3 = sB4[(kb * 4 + 3) * 32 + l];
            uint32_t bj0[8] = { c0.x, c0.y, c0.z, c0.w, c1.x, c1.y, c1.z, c1.w };
            uint32_t bj1[8] = { c2.x, c2.y, c2.z, c2.w, c3.x, c3.y, c3.z, c3.w };

            float4 wA = w1pk[kb * 8 + lr];
            float4 wB = w1pk[kb * 8 + lr + 4];
            #pragma unroll
            for (int mb = 0; mb < 2; mb++) {
                uint32_t afr[4];
                #pragma unroll
                for (int rr = 0; rr < 2; rr++) {
                    int ui = 2 * mb + rr;
                    float ycA = fmaxf(dot3(uc[ui], wA), 0.0f);
                    float ypA = fmaxf(dot3(up[ui], wA), 0.0f);
                    afr[rr]     = f2tf32(0.5f * (ycA + ypA));
                    float ycB = fmaxf(dot3(uc[ui], wB), 0.0f);
                    float ypB = fmaxf(dot3(up[ui], wB), 0.0f);
                    afr[rr + 2] = f2tf32(0.5f * (ycB + ypB));
                }
                #pragma unroll
                for (int nb = 0; nb < 8; nb++)
                    mma_tf32(dacc[mb][nb], afr, bj0[nb], bj1[nb]);
            }
        }

        // ---- epilogue: relu(D + b2) @ Wl, quad-lane reduce, store
        float o[4][3];
        #pragma unroll
        for (int i = 0; i < 4; i++) { o[i][0] = 0.f; o[i][1] = 0.f; o[i][2] = 0.f; }

        #pragma unroll
        for (int mb = 0; mb < 2; mb++)
            #pragma unroll
            for (int nb = 0; nb < 8; nb++) {
                float4 h0 = hdt[nb * 8 + 2 * lr];
                float4 h1 = hdt[nb * 8 + 2 * lr + 1];
                float y;
                y = fmaxf(dacc[mb][nb][0] + h0.x, 0.0f);
                o[2*mb][0] = fmaf(y, h0.y, o[2*mb][0]);
                o[2*mb][1] = fmaf(y, h0.z, o[2*mb][1]);
                o[2*mb][2] = fmaf(y, h0.w, o[2*mb][2]);
                y = fmaxf(dacc[mb][nb][1] + h1.x, 0.0f);
                o[2*mb][0] = fmaf(y, h1.y, o[2*mb][0]);
                o[2*mb][1] = fmaf(y, h1.z, o[2*mb][1]);
                o[2*mb][2] = fmaf(y, h1.w, o[2*mb][2]);
                y = fmaxf(dacc[mb][nb][2] + h0.x, 0.0f);
                o[2*mb+1][0] = fmaf(y, h0.y, o[2*mb+1][0]);
                o[2*mb+1][1] = fmaf(y, h0.z, o[2*mb+1][1]);
                o[2*mb+1][2] = fmaf(y, h0.w, o[2*mb+1][2]);
                y = fmaxf(dacc[mb][nb][3] + h1.x, 0.0f);
                o[2*mb+1][0] = fmaf(y, h1.y, o[2*mb+1][0]);
                o[2*mb+1][1] = fmaf(y, h1.z, o[2*mb+1][1]);
                o[2*mb+1][2] = fmaf(y, h1.w, o[2*mb+1][2]);
            }

        #pragma unroll
        for (int i = 0; i < 4; i++)
            #pragma unroll
            for (int cc = 0; cc < 3; cc++) {
                float v = o[i][cc];
                v += __shfl_xor_sync(0xffffffffu, v, 1);
                v += __shfl_xor_sync(0xffffffffu, v, 2);
                o[i][cc] = v;
            }

        if (lr == 0) {
            #pragma unroll
            for (int i = 0; i < 4; i++) {
                int node = base + c + 8 * i;
                out[3*node+0] = o[i][0] + bl0;
                out[3*node+1] = o[i][1] + bl1;
                out[3*node+2] = o[i][2] + bl2;
            }
        }
    }
}

extern "C" void kernel_launch(void* const* d_in, const int* in_sizes, int n_in,
                              void* d_out, int out_size) {
    // metadata order: node_index, edge_index, W1, b1, W2, b2, Wl, bl
    const float* x  = (const float*)d_in[0];
    const float* W1 = (const float*)d_in[2];
    const float* b1 = (const float*)d_in[3];
    const float* W2 = (const float*)d_in[4];
    const float* b2 = (const float*)d_in[5];
    const float* Wl = (const float*)d_in[6];
    const float* bl = (const float*)d_in[7];
    float* out = (float*)d_out;

    int N  = in_sizes[0] / 3;
    int NT = N / TILE;
    int grid = 3 * 148;
    if (grid > NT) grid = NT;

    gnn_mma<<<grid, TILE>>>(x, W1, b1, W2, b2, Wl, bl, out, NT);
}

// round 7
// speedup vs baseline: 1.3411x; 1.3411x over previous
#include <cuda_runtime.h>
#include <cuda_fp16.h>
#include <cstdint>

#define NPG  1024
#define TILE 128
#define HD   64

__device__ __forceinline__ int prev_node(int j) {
    return ((j & (NPG - 1)) == 0) ? j + NPG - 1 : j - 1;
}

__device__ __forceinline__ uint32_t packh2(float lo, float hi) {
    __half2 h = __floats2half2_rn(lo, hi);
    return *reinterpret_cast<uint32_t*>(&h);
}

__device__ __forceinline__ void mma_f16(float* d, const uint32_t* a, uint32_t b0, uint32_t b1) {
    asm volatile(
        "mma.sync.aligned.m16n8k16.row.col.f32.f16.f16.f32 "
        "{%0,%1,%2,%3}, {%4,%5,%6,%7}, {%8,%9}, {%0,%1,%2,%3};"
        : "+f"(d[0]), "+f"(d[1]), "+f"(d[2]), "+f"(d[3])
        : "r"(a[0]), "r"(a[1]), "r"(a[2]), "r"(a[3]), "r"(b0), "r"(b1));
}

__device__ __forceinline__ float dot3(float4 u, float4 w) {
    return fmaf(u.x, w.x, fmaf(u.y, w.y, fmaf(u.z, w.z, w.w)));
}

__global__ void __launch_bounds__(TILE) gnn_mma16(
    const float* __restrict__ x,
    const float* __restrict__ W1, const float* __restrict__ b1,
    const float* __restrict__ W2, const float* __restrict__ b2,
    const float* __restrict__ Wl, const float* __restrict__ bl,
    float* __restrict__ out, int NT)
{
    __shared__ float4 su[TILE + 4];   // su[i] = avg input of node (base + i - 1)
    __shared__ float4 w1pk[HD];       // {W1[0][k], W1[1][k], W1[2][k], b1[k]}
    __shared__ float  sb2[HD];

    const int t  = threadIdx.x;
    const int l  = t & 31;
    const int w  = t >> 5;
    const int lq = l >> 2;            // 0..7
    const int lr = l & 3;             // 0..3
    const int c  = (w << 5) + lq;     // base local row of this thread's fragments

    if (t < HD) {
        float4 v; v.x = W1[t]; v.y = W1[HD + t]; v.z = W1[2 * HD + t]; v.w = b1[t];
        w1pk[t] = v;
    } else {
        sb2[t - HD] = b2[t - HD];
    }

    // ---- W2 -> per-thread fp16 B fragments (held for whole kernel)
    // kstep s: b0 = {W2[k0][n], W2[k0+1][n]}, b1 = {W2[k0+8][n], W2[k0+9][n]},
    // k0 = 16s + 2lr, n = nb*8 + lq
    uint32_t breg[4][8][2];
    #pragma unroll
    for (int s = 0; s < 4; s++)
        #pragma unroll
        for (int nb = 0; nb < 8; nb++) {
            int n  = nb * 8 + lq;
            int k0 = 16 * s + 2 * lr;
            breg[s][nb][0] = packh2(W2[k0 * HD + n],       W2[(k0 + 1) * HD + n]);
            breg[s][nb][1] = packh2(W2[(k0 + 8) * HD + n], W2[(k0 + 9) * HD + n]);
        }

    // ---- Wl -> head B fragments (cols 3..7 zero)
    uint32_t hb[4][2];
    #pragma unroll
    for (int s = 0; s < 4; s++) {
        int k0 = 16 * s + 2 * lr;
        float w00 = (lq < 3) ? Wl[k0 * 3 + lq] : 0.0f;
        float w01 = (lq < 3) ? Wl[(k0 + 1) * 3 + lq] : 0.0f;
        float w10 = (lq < 3) ? Wl[(k0 + 8) * 3 + lq] : 0.0f;
        float w11 = (lq < 3) ? Wl[(k0 + 9) * 3 + lq] : 0.0f;
        hb[s][0] = packh2(w00, w01);
        hb[s][1] = packh2(w10, w11);
    }

    const float bl0 = bl[0], bl1 = bl[1], bl2 = bl[2];

    for (int tile = blockIdx.x; tile < NT; tile += gridDim.x) {
        const int base = tile * TILE;

        __syncthreads();   // prior tile readers done
        {
            int node = base + t;
            int p = prev_node(node);
            float4 v;
            v.x = 0.5f * (x[3*node+0] + x[3*p+0]);
            v.y = 0.5f * (x[3*node+1] + x[3*p+1]);
            v.z = 0.5f * (x[3*node+2] + x[3*p+2]);
            v.w = 0.0f;
            su[t + 1] = v;
            if (t == 0) {
                int n0 = p, p0 = prev_node(p);
                float4 h;
                h.x = 0.5f * (x[3*n0+0] + x[3*p0+0]);
                h.y = 0.5f * (x[3*n0+1] + x[3*p0+1]);
                h.z = 0.5f * (x[3*n0+2] + x[3*p0+2]);
                h.w = 0.0f;
                su[0] = h;
            }
        }
        __syncthreads();

        // hoist the 8 u-vectors (rows c+{0,8,16,24}, cur & prev)
        float4 up[4], uc[4];
        #pragma unroll
        for (int i = 0; i < 4; i++) {
            int r = c + 8 * i;
            up[i] = su[r];
            uc[i] = su[r + 1];
        }

        float dacc[2][8][4];
        #pragma unroll
        for (int mb = 0; mb < 2; mb++)
            #pragma unroll
            for (int nb = 0; nb < 8; nb++)
                #pragma unroll
                for (int j = 0; j < 4; j++) dacc[mb][nb][j] = 0.0f;

        // ---- main k-loop (4 steps of k16): A fragments on the fly (fp32 math,
        // packed to f16x2), register-resident B
        #pragma unroll
        for (int s = 0; s < 4; s++) {
            int k0 = 16 * s + 2 * lr;
            float4 wa = w1pk[k0];
            float4 wb = w1pk[k0 + 1];
            float4 wc = w1pk[k0 + 8];
            float4 wd = w1pk[k0 + 9];
            #pragma unroll
            for (int mb = 0; mb < 2; mb++) {
                uint32_t afr[4];
                #pragma unroll
                for (int rr = 0; rr < 2; rr++) {
                    int ui = 2 * mb + rr;
                    float va = 0.5f * (fmaxf(dot3(uc[ui], wa), 0.0f) + fmaxf(dot3(up[ui], wa), 0.0f));
                    float vb = 0.5f * (fmaxf(dot3(uc[ui], wb), 0.0f) + fmaxf(dot3(up[ui], wb), 0.0f));
                    float vc = 0.5f * (fmaxf(dot3(uc[ui], wc), 0.0f) + fmaxf(dot3(up[ui], wc), 0.0f));
                    float vd = 0.5f * (fmaxf(dot3(uc[ui], wd), 0.0f) + fmaxf(dot3(up[ui], wd), 0.0f));
                    afr[rr]     = packh2(va, vb);
                    afr[rr + 2] = packh2(vc, vd);
                }
                #pragma unroll
                for (int nb = 0; nb < 8; nb++)
                    mma_f16(dacc[mb][nb], afr, breg[s][nb][0], breg[s][nb][1]);
            }
        }

        // ---- head: relu(D + b2) @ Wl via second MMA (D frags are already
        // in A-fragment layout for k16 — no shuffles)
        float2 b2p[8];
        #pragma unroll
        for (int nb = 0; nb < 8; nb++)
            b2p[nb] = *reinterpret_cast<const float2*>(sb2 + nb * 8 + 2 * lr);

        #pragma unroll
        for (int mb = 0; mb < 2; mb++) {
            float d2[4] = {0.f, 0.f, 0.f, 0.f};
            #pragma unroll
            for (int s = 0; s < 4; s++) {
                int n0 = 2 * s, n1 = 2 * s + 1;
                uint32_t a0 = packh2(fmaxf(dacc[mb][n0][0] + b2p[n0].x, 0.f),
                                     fmaxf(dacc[mb][n0][1] + b2p[n0].y, 0.f));
                uint32_t a1 = packh2(fmaxf(dacc[mb][n0][2] + b2p[n0].x, 0.f),
                                     fmaxf(dacc[mb][n0][3] + b2p[n0].y, 0.f));
                uint32_t a2 = packh2(fmaxf(dacc[mb][n1][0] + b2p[n1].x, 0.f),
                                     fmaxf(dacc[mb][n1][1] + b2p[n1].y, 0.f));
                uint32_t a3 = packh2(fmaxf(dacc[mb][n1][2] + b2p[n1].x, 0.f),
                                     fmaxf(dacc[mb][n1][3] + b2p[n1].y, 0.f));
                uint32_t afr[4] = {a0, a1, a2, a3};
                mma_f16(d2, afr, hb[s][0], hb[s][1]);
            }
            // D2: rows r0 = base+c+16mb (d0,d1 = cols 2lr,2lr+1), r1 = r0+8 (d2,d3)
            int r0 = base + c + 16 * mb;
            int r1 = r0 + 8;
            if (lr == 0) {
                out[3*r0+0] = d2[0] + bl0;
                out[3*r0+1] = d2[1] + bl1;
                out[3*r1+0] = d2[2] + bl0;
                out[3*r1+1] = d2[3] + bl1;
            } else if (lr == 1) {
                out[3*r0+2] = d2[0] + bl2;
                out[3*r1+2] = d2[2] + bl2;
            }
        }
    }
}

extern "C" void kernel_launch(void* const* d_in, const int* in_sizes, int n_in,
                              void* d_out, int out_size) {
    // metadata order: node_index, edge_index, W1, b1, W2, b2, Wl, bl
    const float* x  = (const float*)d_in[0];
    const float* W1 = (const float*)d_in[2];
    const float* b1 = (const float*)d_in[3];
    const float* W2 = (const float*)d_in[4];
    const float* b2 = (const float*)d_in[5];
    const float* Wl = (const float*)d_in[6];
    const float* bl = (const float*)d_in[7];
    float* out = (float*)d_out;

    int N  = in_sizes[0] / 3;
    int NT = N / TILE;
    int grid = 2 * 148;
    if (grid > NT) grid = NT;

    gnn_mma16<<<grid, TILE>>>(x, W1, b1, W2, b2, Wl, bl, out, NT);
}

// round 8
// speedup vs baseline: 1.3465x; 1.0040x over previous
#include <cuda_runtime.h>
#include <cuda_fp16.h>
#include <cstdint>

#define NPG  1024
#define TILE 128
#define HD   64

__device__ __forceinline__ int prev_node(int j) {
    return ((j & (NPG - 1)) == 0) ? j + NPG - 1 : j - 1;
}

__device__ __forceinline__ uint32_t packh2(float lo, float hi) {
    __half2 h = __floats2half2_rn(lo, hi);
    return *reinterpret_cast<uint32_t*>(&h);
}

__device__ __forceinline__ void mma_f16(float* d, const uint32_t* a, uint32_t b0, uint32_t b1) {
    asm volatile(
        "mma.sync.aligned.m16n8k16.row.col.f32.f16.f16.f32 "
        "{%0,%1,%2,%3}, {%4,%5,%6,%7}, {%8,%9}, {%0,%1,%2,%3};"
        : "+f"(d[0]), "+f"(d[1]), "+f"(d[2]), "+f"(d[3])
        : "r"(a[0]), "r"(a[1]), "r"(a[2]), "r"(a[3]), "r"(b0), "r"(b1));
}

__device__ __forceinline__ float dot3(float4 u, float4 w) {
    return fmaf(u.x, w.x, fmaf(u.y, w.y, fmaf(u.z, w.z, w.w)));
}

__global__ void __launch_bounds__(TILE, 3) gnn_mma16(
    const float* __restrict__ x,
    const float* __restrict__ W1, const float* __restrict__ b1,
    const float* __restrict__ W2, const float* __restrict__ b2,
    const float* __restrict__ Wl, const float* __restrict__ bl,
    float* __restrict__ out, int NT)
{
    __shared__ float4 su[TILE + 4];   // su[i] = avg input of node (base + i - 1)
    __shared__ float4 w1pk[HD];       // {W1[0][k], W1[1][k], W1[2][k], b1[k]}
    __shared__ float  sb2[HD];

    const int t  = threadIdx.x;
    const int l  = t & 31;
    const int w  = t >> 5;
    const int lq = l >> 2;            // 0..7
    const int lr = l & 3;             // 0..3
    const int c  = (w << 5) + lq;     // base local row of this thread's fragments

    if (t < HD) {
        float4 v; v.x = W1[t]; v.y = W1[HD + t]; v.z = W1[2 * HD + t]; v.w = b1[t];
        w1pk[t] = v;
    } else {
        sb2[t - HD] = b2[t - HD];
    }

    // ---- W2 -> per-thread fp16 B fragments (held for whole kernel)
    uint32_t breg[4][8][2];
    #pragma unroll
    for (int s = 0; s < 4; s++)
        #pragma unroll
        for (int nb = 0; nb < 8; nb++) {
            int n  = nb * 8 + lq;
            int k0 = 16 * s + 2 * lr;
            breg[s][nb][0] = packh2(W2[k0 * HD + n],       W2[(k0 + 1) * HD + n]);
            breg[s][nb][1] = packh2(W2[(k0 + 8) * HD + n], W2[(k0 + 9) * HD + n]);
        }

    // ---- Wl -> head B fragments (cols 3..7 zero)
    uint32_t hb[4][2];
    #pragma unroll
    for (int s = 0; s < 4; s++) {
        int k0 = 16 * s + 2 * lr;
        float w00 = (lq < 3) ? Wl[k0 * 3 + lq] : 0.0f;
        float w01 = (lq < 3) ? Wl[(k0 + 1) * 3 + lq] : 0.0f;
        float w10 = (lq < 3) ? Wl[(k0 + 8) * 3 + lq] : 0.0f;
        float w11 = (lq < 3) ? Wl[(k0 + 9) * 3 + lq] : 0.0f;
        hb[s][0] = packh2(w00, w01);
        hb[s][1] = packh2(w10, w11);
    }

    const float bl0 = bl[0], bl1 = bl[1], bl2 = bl[2];

    for (int tile = blockIdx.x; tile < NT; tile += gridDim.x) {
        const int base = tile * TILE;

        __syncthreads();   // prior tile readers done
        {
            int node = base + t;
            int p = prev_node(node);
            float4 v;
            v.x = 0.5f * (x[3*node+0] + x[3*p+0]);
            v.y = 0.5f * (x[3*node+1] + x[3*p+1]);
            v.z = 0.5f * (x[3*node+2] + x[3*p+2]);
            v.w = 0.0f;
            su[t + 1] = v;
            if (t == 0) {
                int n0 = p, p0 = prev_node(p);
                float4 h;
                h.x = 0.5f * (x[3*n0+0] + x[3*p0+0]);
                h.y = 0.5f * (x[3*n0+1] + x[3*p0+1]);
                h.z = 0.5f * (x[3*n0+2] + x[3*p0+2]);
                h.w = 0.0f;
                su[0] = h;
            }
        }
        __syncthreads();

        // ---- mb outer: halves live accumulator footprint (epilogue per mb)
        #pragma unroll
        for (int mb = 0; mb < 2; mb++) {
            // u vectors for this mb's two row groups (c+16mb, c+16mb+8)
            float4 up[2], uc[2];
            #pragma unroll
            for (int rr = 0; rr < 2; rr++) {
                int r = c + 16 * mb + 8 * rr;
                up[rr] = su[r];
                uc[rr] = su[r + 1];
            }

            float dacc[8][4];
            #pragma unroll
            for (int nb = 0; nb < 8; nb++)
                #pragma unroll
                for (int j = 0; j < 4; j++) dacc[nb][j] = 0.0f;

            // main k-loop (4 steps of k16)
            #pragma unroll
            for (int s = 0; s < 4; s++) {
                int k0 = 16 * s + 2 * lr;
                float4 wa = w1pk[k0];
                float4 wb = w1pk[k0 + 1];
                float4 wc = w1pk[k0 + 8];
                float4 wd = w1pk[k0 + 9];
                uint32_t afr[4];
                #pragma unroll
                for (int rr = 0; rr < 2; rr++) {
                    float va = 0.5f * (fmaxf(dot3(uc[rr], wa), 0.0f) + fmaxf(dot3(up[rr], wa), 0.0f));
                    float vb = 0.5f * (fmaxf(dot3(uc[rr], wb), 0.0f) + fmaxf(dot3(up[rr], wb), 0.0f));
                    float vc = 0.5f * (fmaxf(dot3(uc[rr], wc), 0.0f) + fmaxf(dot3(up[rr], wc), 0.0f));
                    float vd = 0.5f * (fmaxf(dot3(uc[rr], wd), 0.0f) + fmaxf(dot3(up[rr], wd), 0.0f));
                    afr[rr]     = packh2(va, vb);
                    afr[rr + 2] = packh2(vc, vd);
                }
                #pragma unroll
                for (int nb = 0; nb < 8; nb++)
                    mma_f16(dacc[nb], afr, breg[s][nb][0], breg[s][nb][1]);
            }

            // ---- head for this mb: relu(D + b2) @ Wl via second MMA
            float d2[4] = {0.f, 0.f, 0.f, 0.f};
            #pragma unroll
            for (int s = 0; s < 4; s++) {
                int n0 = 2 * s, n1 = 2 * s + 1;
                float2 bp0 = *reinterpret_cast<const float2*>(sb2 + n0 * 8 + 2 * lr);
                float2 bp1 = *reinterpret_cast<const float2*>(sb2 + n1 * 8 + 2 * lr);
                uint32_t a0 = packh2(fmaxf(dacc[n0][0] + bp0.x, 0.f),
                                     fmaxf(dacc[n0][1] + bp0.y, 0.f));
                uint32_t a1 = packh2(fmaxf(dacc[n0][2] + bp0.x, 0.f),
                                     fmaxf(dacc[n0][3] + bp0.y, 0.f));
                uint32_t a2 = packh2(fmaxf(dacc[n1][0] + bp1.x, 0.f),
                                     fmaxf(dacc[n1][1] + bp1.y, 0.f));
                uint32_t a3 = packh2(fmaxf(dacc[n1][2] + bp1.x, 0.f),
                                     fmaxf(dacc[n1][3] + bp1.y, 0.f));
                uint32_t afr[4] = {a0, a1, a2, a3};
                mma_f16(d2, afr, hb[s][0], hb[s][1]);
            }
            int r0 = base + c + 16 * mb;
            int r1 = r0 + 8;
            if (lr == 0) {
                out[3*r0+0] = d2[0] + bl0;
                out[3*r0+1] = d2[1] + bl1;
                out[3*r1+0] = d2[2] + bl0;
                out[3*r1+1] = d2[3] + bl1;
            } else if (lr == 1) {
                out[3*r0+2] = d2[0] + bl2;
                out[3*r1+2] = d2[2] + bl2;
            }
        }
    }
}

extern "C" void kernel_launch(void* const* d_in, const int* in_sizes, int n_in,
                              void* d_out, int out_size) {
    // metadata order: node_index, edge_index, W1, b1, W2, b2, Wl, bl
    const float* x  = (const float*)d_in[0];
    const float* W1 = (const float*)d_in[2];
    const float* b1 = (const float*)d_in[3];
    const float* W2 = (const float*)d_in[4];
    const float* b2 = (const float*)d_in[5];
    const float* Wl = (const float*)d_in[6];
    const float* bl = (const float*)d_in[7];
    float* out = (float*)d_out;

    int N  = in_sizes[0] / 3;
    int NT = N / TILE;
    int grid = 3 * 148;
    if (grid > NT) grid = NT;

    gnn_mma16<<<grid, TILE>>>(x, W1, b1, W2, b2, Wl, bl, out, NT);
}

// round 9
// speedup vs baseline: 1.5566x; 1.1561x over previous
#include <cuda_runtime.h>
#include <cuda_fp16.h>
#include <cstdint>

#define NPG  1024
#define HD   64
#define FULL 0xffffffffu

__device__ __forceinline__ int prev_node(int j) {
    return ((j & (NPG - 1)) == 0) ? j + NPG - 1 : j - 1;
}

__device__ __forceinline__ uint32_t packh2(float lo, float hi) {
    __half2 h = __floats2half2_rn(lo, hi);
    return *reinterpret_cast<uint32_t*>(&h);
}

__device__ __forceinline__ float lo_of(float v) {
    return v - __half2float(__float2half_rn(v));
}

__device__ __forceinline__ uint32_t h2relu(uint32_t a) {
    __half2 r = __hmax2(*reinterpret_cast<__half2*>(&a), __float2half2_rn(0.0f));
    return *reinterpret_cast<uint32_t*>(&r);
}

__device__ __forceinline__ uint32_t h2avg(uint32_t a, uint32_t b) {
    __half2 r = __hmul2(__hadd2(*reinterpret_cast<__half2*>(&a),
                                *reinterpret_cast<__half2*>(&b)),
                        __float2half2_rn(0.5f));
    return *reinterpret_cast<uint32_t*>(&r);
}

__device__ __forceinline__ void mma_f16(float* d, uint32_t a0, uint32_t a1,
                                        uint32_t a2, uint32_t a3,
                                        uint32_t b0, uint32_t b1) {
    asm volatile(
        "mma.sync.aligned.m16n8k16.row.col.f32.f16.f16.f32 "
        "{%0,%1,%2,%3}, {%4,%5,%6,%7}, {%8,%9}, {%0,%1,%2,%3};"
        : "+f"(d[0]), "+f"(d[1]), "+f"(d[2]), "+f"(d[3])
        : "r"(a0), "r"(a1), "r"(a2), "r"(a3), "r"(b0), "r"(b1));
}

__global__ void __launch_bounds__(128) gnn_warp(
    const float* __restrict__ x,
    const float* __restrict__ W1, const float* __restrict__ b1,
    const float* __restrict__ W2, const float* __restrict__ b2,
    const float* __restrict__ Wl, const float* __restrict__ bl,
    float* __restrict__ out, int nseg)
{
    __shared__ float4 w1pk[HD];   // column c of W1 + bias: {W1[0][c],W1[1][c],W1[2][c],b1[c]}
    __shared__ float  sb2[HD];

    const int t  = threadIdx.x;
    const int l  = t & 31;
    const int w  = t >> 5;
    const int lq = l >> 2;            // 0..7
    const int lr = l & 3;             // 0..3

    if (t < HD) {
        float4 v; v.x = W1[t]; v.y = W1[HD + t]; v.z = W1[2 * HD + t]; v.w = b1[t];
        w1pk[t] = v;
    } else if (t < 2 * HD) {
        sb2[t - HD] = b2[t - HD];
    }
    __syncthreads();   // once, outside the tile loop

    // ---- stage-1 B fragments: W1' rows 0..7 = [hi0,hi1,hi2,b1hi, hi0,hi1,hi2,0],
    //                           rows 8..15  = [lo0,lo1,lo2,b1lo, 0,0,0,0]
    uint32_t w1b[8][2];
    #pragma unroll
    for (int nb = 0; nb < 8; nb++) {
        int n = nb * 8 + lq;
        float w0 = W1[n], w1v = W1[HD + n], w2v = W1[2 * HD + n], bb = b1[n];
        uint32_t bhi, blo;
        if (lr == 0)      { bhi = packh2(w0, w1v);  blo = packh2(lo_of(w0), lo_of(w1v)); }
        else if (lr == 1) { bhi = packh2(w2v, bb);  blo = packh2(lo_of(w2v), lo_of(bb)); }
        else if (lr == 2) { bhi = packh2(w0, w1v);  blo = 0; }
        else              { bhi = packh2(w2v, 0.f); blo = 0; }
        w1b[nb][0] = bhi;
        w1b[nb][1] = blo;
    }

    // ---- stage-2 B fragments (W2, fp16) — as R8
    uint32_t breg[4][8][2];
    #pragma unroll
    for (int s = 0; s < 4; s++)
        #pragma unroll
        for (int nb = 0; nb < 8; nb++) {
            int n  = nb * 8 + lq;
            int k0 = 16 * s + 2 * lr;
            breg[s][nb][0] = packh2(W2[k0 * HD + n],       W2[(k0 + 1) * HD + n]);
            breg[s][nb][1] = packh2(W2[(k0 + 8) * HD + n], W2[(k0 + 9) * HD + n]);
        }

    // ---- head B fragments (Wl, cols 3..7 zero) — as R8
    uint32_t hb[4][2];
    #pragma unroll
    for (int s = 0; s < 4; s++) {
        int k0 = 16 * s + 2 * lr;
        float w00 = (lq < 3) ? Wl[k0 * 3 + lq] : 0.0f;
        float w01 = (lq < 3) ? Wl[(k0 + 1) * 3 + lq] : 0.0f;
        float w10 = (lq < 3) ? Wl[(k0 + 8) * 3 + lq] : 0.0f;
        float w11 = (lq < 3) ? Wl[(k0 + 9) * 3 + lq] : 0.0f;
        hb[s][0] = packh2(w00, w01);
        hb[s][1] = packh2(w10, w11);
    }

    const float bl0 = bl[0], bl1 = bl[1], bl2 = bl[2];
    const int gw    = blockIdx.x * 4 + w;
    const int nwarp = gridDim.x * 4;

    for (int seg = gw; seg < nseg; seg += nwarp) {
        const int base = seg * 32;

        // ---- per-lane ring-averaged input u (fp32), split hi/lo
        const int n  = base + l;
        const int p  = prev_node(n);
        const float ux = 0.5f * (x[3*n+0] + x[3*p+0]);
        const float uy = 0.5f * (x[3*n+1] + x[3*p+1]);
        const float uz = 0.5f * (x[3*n+2] + x[3*p+2]);
        const uint32_t uhi_xy = packh2(ux, uy);
        const uint32_t uhi_z1 = packh2(uz, 1.0f);
        const uint32_t ulo_xy = packh2(lo_of(ux), lo_of(uy));
        const uint32_t ulo_z0 = packh2(lo_of(uz), 0.0f);

        // ---- halo node (row -1): z computed scalar (used by lq==0 at mb=0)
        uint32_t zl_halo[8];
        {
            const int H  = prev_node(base);
            const int pH = prev_node(H);
            const float hx = 0.5f * (x[3*H+0] + x[3*pH+0]);
            const float hy = 0.5f * (x[3*H+1] + x[3*pH+1]);
            const float hz = 0.5f * (x[3*H+2] + x[3*pH+2]);
            #pragma unroll
            for (int nb = 0; nb < 8; nb++) {
                int c0 = nb * 8 + 2 * lr;
                float4 wc0 = w1pk[c0];
                float4 wc1 = w1pk[c0 + 1];
                float h0 = fmaf(hx, wc0.x, fmaf(hy, wc0.y, fmaf(hz, wc0.z, wc0.w)));
                float h1 = fmaf(hx, wc1.x, fmaf(hy, wc1.y, fmaf(hz, wc1.z, wc1.w)));
                zl_halo[nb] = packh2(fmaxf(h0, 0.f), fmaxf(h1, 0.f));
            }
        }

        uint32_t saved15[8];   // z row 15 (valid in lq==0 lanes after mb=0)

        #pragma unroll
        for (int mb = 0; mb < 2; mb++) {
            const int r0 = 16 * mb + lq;
            const int r1 = r0 + 8;

            // ---- stage-1 A fragments: shuffle u from row lanes, select by lr
            uint32_t s0a = __shfl_sync(FULL, uhi_xy, r0);
            uint32_t s0b = __shfl_sync(FULL, uhi_z1, r0);
            uint32_t s0c = __shfl_sync(FULL, ulo_xy, r0);
            uint32_t s0d = __shfl_sync(FULL, ulo_z0, r0);
            uint32_t s1a = __shfl_sync(FULL, uhi_xy, r1);
            uint32_t s1b = __shfl_sync(FULL, uhi_z1, r1);
            uint32_t s1c = __shfl_sync(FULL, ulo_xy, r1);
            uint32_t s1d = __shfl_sync(FULL, ulo_z0, r1);
            uint32_t a0 = (lr == 0) ? s0a : (lr == 1) ? s0b : (lr == 2) ? s0c : s0d;
            uint32_t a1 = (lr == 0) ? s1a : (lr == 1) ? s1b : (lr == 2) ? s1c : s1d;
            uint32_t a2 = (lr == 0) ? s0a : (lr == 1) ? s0b : 0u;
            uint32_t a3 = (lr == 0) ? s1a : (lr == 1) ? s1b : 0u;

            // ---- stage-1 MMA: h[32 x 64]
            float hD[8][4];
            #pragma unroll
            for (int nb = 0; nb < 8; nb++) {
                hD[nb][0] = 0.f; hD[nb][1] = 0.f; hD[nb][2] = 0.f; hD[nb][3] = 0.f;
                mma_f16(hD[nb], a0, a1, a2, a3, w1b[nb][0], w1b[nb][1]);
            }

            // ---- relu-pack, ring shift via shuffle, average -> stage-2 A frags
            uint32_t al[8], ah[8];
            #pragma unroll
            for (int nb = 0; nb < 8; nb++) {
                uint32_t zl = h2relu(packh2(hD[nb][0], hD[nb][1]));  // row r0
                uint32_t zh = h2relu(packh2(hD[nb][2], hD[nb][3]));  // row r1
                uint32_t zls = __shfl_sync(FULL, zl, (l + 28) & 31);
                uint32_t zhs = __shfl_sync(FULL, zh, (l + 28) & 31);
                uint32_t zlp, zhp;
                if (lq == 0) {
                    zlp = (mb == 0) ? zl_halo[nb] : saved15[nb];
                    zhp = zls;     // = z row 16mb+7 (lane lq=7's zl)
                } else {
                    zlp = zls;     // row r0-1
                    zhp = zhs;     // row r1-1
                }
                if (mb == 0) saved15[nb] = zhs;   // lq==0: z row 15
                al[nb] = h2avg(zl, zlp);
                ah[nb] = h2avg(zh, zhp);
            }

            // ---- stage-2 MMA: y2 = zavg @ W2
            float dacc[8][4];
            #pragma unroll
            for (int nb = 0; nb < 8; nb++) {
                dacc[nb][0] = 0.f; dacc[nb][1] = 0.f; dacc[nb][2] = 0.f; dacc[nb][3] = 0.f;
            }
            #pragma unroll
            for (int s = 0; s < 4; s++) {
                #pragma unroll
                for (int nb = 0; nb < 8; nb++)
                    mma_f16(dacc[nb], al[2*s], ah[2*s], al[2*s+1], ah[2*s+1],
                            breg[s][nb][0], breg[s][nb][1]);
            }

            // ---- head: relu(y2 + b2) @ Wl via MMA (D frags already A-layout)
            float d2[4] = {0.f, 0.f, 0.f, 0.f};
            #pragma unroll
            for (int s = 0; s < 4; s++) {
                int n0 = 2 * s, n1 = 2 * s + 1;
                float2 bp0 = *reinterpret_cast<const float2*>(sb2 + n0 * 8 + 2 * lr);
                float2 bp1 = *reinterpret_cast<const float2*>(sb2 + n1 * 8 + 2 * lr);
                uint32_t e0 = packh2(fmaxf(dacc[n0][0] + bp0.x, 0.f),
                                     fmaxf(dacc[n0][1] + bp0.y, 0.f));
                uint32_t e1 = packh2(fmaxf(dacc[n0][2] + bp0.x, 0.f),
                                     fmaxf(dacc[n0][3] + bp0.y, 0.f));
                uint32_t e2 = packh2(fmaxf(dacc[n1][0] + bp1.x, 0.f),
                                     fmaxf(dacc[n1][1] + bp1.y, 0.f));
                uint32_t e3 = packh2(fmaxf(dacc[n1][2] + bp1.x, 0.f),
                                     fmaxf(dacc[n1][3] + bp1.y, 0.f));
                mma_f16(d2, e0, e1, e2, e3, hb[s][0], hb[s][1]);
            }

            const int g0 = base + r0;
            const int g1 = base + r1;
            if (lr == 0) {
                out[3*g0+0] = d2[0] + bl0;
                out[3*g0+1] = d2[1] + bl1;
                out[3*g1+0] = d2[2] + bl0;
                out[3*g1+1] = d2[3] + bl1;
            } else if (lr == 1) {
                out[3*g0+2] = d2[0] + bl2;
                out[3*g1+2] = d2[2] + bl2;
            }
        }
    }
}

extern "C" void kernel_launch(void* const* d_in, const int* in_sizes, int n_in,
                              void* d_out, int out_size) {
    // metadata order: node_index, edge_index, W1, b1, W2, b2, Wl, bl
    const float* x  = (const float*)d_in[0];
    const float* W1 = (const float*)d_in[2];
    const float* b1 = (const float*)d_in[3];
    const float* W2 = (const float*)d_in[4];
    const float* b2 = (const float*)d_in[5];
    const float* Wl = (const float*)d_in[6];
    const float* bl = (const float*)d_in[7];
    float* out = (float*)d_out;

    int N    = in_sizes[0] / 3;
    int nseg = N / 32;
    int grid = 2 * 148;
    if (grid * 4 > nseg) grid = (nseg + 3) / 4;

    gnn_warp<<<grid, 128>>>(x, W1, b1, W2, b2, Wl, bl, out, nseg);
}